// round 1
// baseline (speedup 1.0000x reference)
#include <cuda_runtime.h>
#include <cstdint>
#include <math.h>

#define XCOLS   111
#define DOUT    256
#define OUTCOLS (22*256 + 111)   // 5743
#define TILE_R  64
#define GSTRIDE 260              // 260 mod 32 == 4  -> conflict-free A-frag loads
#define WSTRIDE 264              // 264 mod 32 == 8  -> conflict-free B-frag loads
#define KCHUNK  64
#define NTHREADS 256

// Per-part tables (output part p covers out cols [p*256, p*256+256); input cols are
// a contiguous partition of x's 111 columns in exactly output order).
__constant__ int c_in_off[22] = {0,3,6,9,43,46,49,52,61,64,67,70,74,77,80,83,92,95,98,101,105,108};
__constant__ int c_din[22]    = {3,3,3,34,3,3,3, 9,3,3,3, 4,3,3,3, 9,3,3,3,  4,  3,  3};
// weight set: 0=pv 1=rot 2=st 3=pad   (2,3 have a final LayerNorm)
__constant__ int c_wset[22]   = {0,0,0, 3,0,0,0, 1,0,0,0, 2,0,0,0, 1,0,0,0,  2,  0,  0};

struct Params {
    const float* x;
    const float* W1[4];
    const float* b1[4];
    const float* g1[4];
    const float* bt1[4];
    const float* W2[4];
    const float* b2[4];
    const float* g2[4];
    const float* bt2[4];
    float* out;
    int rows;
};

__device__ __forceinline__ uint32_t f2tf32(float v) {
    uint32_t r;
    asm("cvt.rna.tf32.f32 %0, %1;" : "=r"(r) : "f"(v));
    return r;
}

__device__ __forceinline__ void mma_tf32(float c[4], const uint32_t a[4], uint32_t b0, uint32_t b1) {
    asm volatile(
        "mma.sync.aligned.m16n8k8.row.col.f32.tf32.tf32.f32 "
        "{%0,%1,%2,%3}, {%4,%5,%6,%7}, {%8,%9}, {%0,%1,%2,%3};\n"
        : "+f"(c[0]), "+f"(c[1]), "+f"(c[2]), "+f"(c[3])
        : "r"(a[0]), "r"(a[1]), "r"(a[2]), "r"(a[3]), "r"(b0), "r"(b1));
}

// Row-wise LayerNorm (+ optional exact GELU) over g[TILE_R][GSTRIDE] (256 valid cols).
// Warp w handles rows w, w+8, ...
__device__ __forceinline__ void ln_rows(float* g, const float* gamma, const float* beta,
                                        bool do_gelu, int tid) {
    int warp = tid >> 5, lane = tid & 31;
    for (int r = warp; r < TILE_R; r += 8) {
        float v[8];
        float s = 0.f;
        #pragma unroll
        for (int j = 0; j < 8; j++) { v[j] = g[r*GSTRIDE + j*32 + lane]; s += v[j]; }
        #pragma unroll
        for (int o = 16; o; o >>= 1) s += __shfl_xor_sync(0xffffffffu, s, o);
        float mean = s * (1.f/256.f);
        float s2 = 0.f;
        #pragma unroll
        for (int j = 0; j < 8; j++) { float d = v[j] - mean; s2 += d*d; }
        #pragma unroll
        for (int o = 16; o; o >>= 1) s2 += __shfl_xor_sync(0xffffffffu, s2, o);
        float rstd = rsqrtf(s2 * (1.f/256.f) + 1e-5f);
        #pragma unroll
        for (int j = 0; j < 8; j++) {
            float hv = (v[j] - mean) * rstd * gamma[j*32 + lane] + beta[j*32 + lane];
            if (do_gelu) hv = 0.5f * hv * (1.f + erff(hv * 0.70710678f));
            g[r*GSTRIDE + j*32 + lane] = hv;
        }
    }
}

__global__ __launch_bounds__(NTHREADS, 1)
void phys_kernel(Params p) {
    const int part = blockIdx.y;
    const int r0 = blockIdx.x * TILE_R;
    const int tid = threadIdx.x;

    // ---- part 22: raw x passthrough into out[:, 5632:5743] ----
    if (part == 22) {
        for (int i = tid; i < TILE_R * XCOLS; i += NTHREADS) {
            int r = i / XCOLS, c = i - r * XCOLS;
            p.out[(size_t)(r0 + r) * OUTCOLS + 22*256 + c] =
                p.x[(size_t)(r0 + r) * XCOLS + c];
        }
        return;
    }

    extern __shared__ float smem[];
    float* g   = smem;                         // [TILE_R][GSTRIDE]
    float* buf = g + TILE_R * GSTRIDE;         // union: {xs + W1} or {W2 chunk [KCHUNK][WSTRIDE]}
    float* vb1  = buf + (size_t)KCHUNK * WSTRIDE;
    float* vg1  = vb1 + 256;
    float* vbt1 = vg1 + 256;
    float* vb2  = vbt1 + 256;
    float* vg2  = vb2 + 256;
    float* vbt2 = vg2 + 256;

    const int ws   = c_wset[part];
    const int din  = c_din[part];
    const int ioff = c_in_off[part];
    const bool fln = (ws == 2 || ws == 3);

    // per-feature vectors
    vb1[tid]  = p.b1[ws][tid];
    vg1[tid]  = p.g1[ws][tid];
    vbt1[tid] = p.bt1[ws][tid];
    vb2[tid]  = p.b2[ws][tid];
    if (fln) { vg2[tid] = p.g2[ws][tid]; vbt2[tid] = p.bt2[ws][tid]; }

    // ---- Phase A: stage-1 linear + LN + exact GELU -> g[64][256] fp32 ----
    float* xs = buf;               // [TILE_R][36]  (padded stride)
    float* w1 = buf + TILE_R * 36; // [din][256]
    for (int i = tid; i < TILE_R * din; i += NTHREADS) {
        int r = i / din, c = i - r * din;
        xs[r*36 + c] = p.x[(size_t)(r0 + r) * XCOLS + ioff + c];
    }
    for (int i = tid; i < din * 256; i += NTHREADS) w1[i] = p.W1[ws][i];
    __syncthreads();

    // h[r][tid] = b1[tid] + sum_i xs[r][i] * W1[i][tid]
    for (int r = 0; r < TILE_R; ++r) {
        float acc = vb1[tid];
        for (int i = 0; i < din; ++i)
            acc = fmaf(xs[r*36 + i], w1[i*256 + tid], acc);
        g[r*GSTRIDE + tid] = acc;
    }
    __syncthreads();

    ln_rows(g, vg1, vbt1, /*gelu=*/true, tid);
    __syncthreads();

    // ---- Phase B: [64,256] @ W2[256,256] with tf32 mma.sync ----
    // 8 warps: 2 row-groups x 4 col-groups; warp tile = 32 rows x 64 cols
    const int warp = tid >> 5, lane = tid & 31;
    const int rowGroup = warp >> 2;      // 0..1
    const int colGroup = warp & 3;       // 0..3
    const int gid = lane >> 2, tig = lane & 3;

    float acc[2][8][4];
    #pragma unroll
    for (int mt = 0; mt < 2; mt++)
        #pragma unroll
        for (int nt = 0; nt < 8; nt++)
            #pragma unroll
            for (int q = 0; q < 4; q++) acc[mt][nt][q] = 0.f;

    float* w2s = buf;                    // [KCHUNK][WSTRIDE]
    const float* W2 = p.W2[ws];

    for (int k0 = 0; k0 < 256; k0 += KCHUNK) {
        __syncthreads();   // previous chunk fully consumed
        for (int i = tid; i < KCHUNK * 256; i += NTHREADS) {
            int kk = i >> 8, c = i & 255;
            w2s[kk*WSTRIDE + c] = W2[(size_t)(k0 + kk) * 256 + c];
        }
        __syncthreads();

        #pragma unroll
        for (int ks = 0; ks < KCHUNK; ks += 8) {
            uint32_t a[2][4];
            #pragma unroll
            for (int mt = 0; mt < 2; mt++) {
                int rbase = rowGroup*32 + mt*16;
                a[mt][0] = f2tf32(g[(rbase + gid    )*GSTRIDE + k0 + ks + tig    ]);
                a[mt][1] = f2tf32(g[(rbase + gid + 8)*GSTRIDE + k0 + ks + tig    ]);
                a[mt][2] = f2tf32(g[(rbase + gid    )*GSTRIDE + k0 + ks + tig + 4]);
                a[mt][3] = f2tf32(g[(rbase + gid + 8)*GSTRIDE + k0 + ks + tig + 4]);
            }
            #pragma unroll
            for (int nt = 0; nt < 8; nt++) {
                int nbase = colGroup*64 + nt*8;
                uint32_t b0 = f2tf32(w2s[(ks + tig    )*WSTRIDE + nbase + gid]);
                uint32_t b1 = f2tf32(w2s[(ks + tig + 4)*WSTRIDE + nbase + gid]);
                mma_tf32(acc[0][nt], a[0], b0, b1);
                mma_tf32(acc[1][nt], a[1], b0, b1);
            }
        }
    }

    // ---- Epilogue: stage to smem (+b2), optional final LN, coalesced store ----
    __syncthreads();   // everyone done reading g as A operand
    #pragma unroll
    for (int mt = 0; mt < 2; mt++) {
        int rbase = rowGroup*32 + mt*16;
        #pragma unroll
        for (int nt = 0; nt < 8; nt++) {
            int nbase = colGroup*64 + nt*8;
            int cc = nbase + tig*2;
            g[(rbase + gid    )*GSTRIDE + cc    ] = acc[mt][nt][0] + vb2[cc    ];
            g[(rbase + gid    )*GSTRIDE + cc + 1] = acc[mt][nt][1] + vb2[cc + 1];
            g[(rbase + gid + 8)*GSTRIDE + cc    ] = acc[mt][nt][2] + vb2[cc    ];
            g[(rbase + gid + 8)*GSTRIDE + cc + 1] = acc[mt][nt][3] + vb2[cc + 1];
        }
    }
    __syncthreads();

    if (fln) {
        ln_rows(g, vg2, vbt2, /*gelu=*/false, tid);
        __syncthreads();
    }

    const size_t col0 = (size_t)part * 256;
    for (int r = 0; r < TILE_R; ++r)
        p.out[(size_t)(r0 + r) * OUTCOLS + col0 + tid] = g[r*GSTRIDE + tid];
}

extern "C" void kernel_launch(void* const* d_in, const int* in_sizes, int n_in,
                              void* d_out, int out_size) {
    // input order follows the reference signature:
    // 0:x  1-6:pv(W1,b1,g1,bt1,W2,b2)  7-12:rot  13-20:pad(+g2,bt2)  21-28:st(+g2,bt2)
    const int w1i[4]  = {1, 7, 21, 13};
    const int b1i[4]  = {2, 8, 22, 14};
    const int g1i[4]  = {3, 9, 23, 15};
    const int bt1i[4] = {4, 10, 24, 16};
    const int w2i[4]  = {5, 11, 25, 17};
    const int b2i[4]  = {6, 12, 26, 18};

    Params p;
    p.x = (const float*)d_in[0];
    for (int s = 0; s < 4; s++) {
        p.W1[s]  = (const float*)d_in[w1i[s]];
        p.b1[s]  = (const float*)d_in[b1i[s]];
        p.g1[s]  = (const float*)d_in[g1i[s]];
        p.bt1[s] = (const float*)d_in[bt1i[s]];
        p.W2[s]  = (const float*)d_in[w2i[s]];
        p.b2[s]  = (const float*)d_in[b2i[s]];
        p.g2[s]  = nullptr;
        p.bt2[s] = nullptr;
    }
    p.g2[2]  = (const float*)d_in[27];  // st_g2
    p.bt2[2] = (const float*)d_in[28];  // st_bt2
    p.g2[3]  = (const float*)d_in[19];  // pad_g2
    p.bt2[3] = (const float*)d_in[20];  // pad_bt2
    p.out = (float*)d_out;

    int rows = in_sizes[0] / XCOLS;
    p.rows = rows;
    int rtiles = (rows + TILE_R - 1) / TILE_R;

    size_t smem_bytes = (size_t)(TILE_R * GSTRIDE + KCHUNK * WSTRIDE + 6 * 256) * sizeof(float);
    cudaFuncSetAttribute(phys_kernel, cudaFuncAttributeMaxDynamicSharedMemorySize,
                         (int)smem_bytes);

    dim3 grid(rtiles, 23);
    phys_kernel<<<grid, NTHREADS, smem_bytes>>>(p);
}

// round 2
// speedup vs baseline: 2.0827x; 2.0827x over previous
#include <cuda_runtime.h>
#include <cstdint>
#include <math.h>

#define XCOLS    111
#define OUTCOLS  (22*256 + 111)   // 5743
#define TILE_R   64
#define GSTRIDE  260              // mod 32 == 4 -> conflict-free A-frag loads
#define WSTRIDE  264              // mod 32 == 8 -> conflict-free B-frag loads
#define KCHUNK   32
#define NCHUNKS  8                // 256 / 32
#define NTHREADS 512

__constant__ int c_in_off[22] = {0,3,6,9,43,46,49,52,61,64,67,70,74,77,80,83,92,95,98,101,105,108};
__constant__ int c_din[22]    = {3,3,3,34,3,3,3, 9,3,3,3, 4,3,3,3, 9,3,3,3,  4,  3,  3};
__constant__ int c_wset[22]   = {0,0,0, 3,0,0,0, 1,0,0,0, 2,0,0,0, 1,0,0,0,  2,  0,  0};

struct Params {
    const float* x;
    const float* W1[4];
    const float* b1[4];
    const float* g1[4];
    const float* bt1[4];
    const float* W2[4];
    const float* b2[4];
    const float* g2[4];
    const float* bt2[4];
    float* out;
    int rows;
};

__device__ __forceinline__ uint32_t f2tf32(float v) {
    uint32_t r;
    asm("cvt.rna.tf32.f32 %0, %1;" : "=r"(r) : "f"(v));
    return r;
}

__device__ __forceinline__ void mma_tf32(float c[4], const uint32_t a[4], uint32_t b0, uint32_t b1) {
    asm volatile(
        "mma.sync.aligned.m16n8k8.row.col.f32.tf32.tf32.f32 "
        "{%0,%1,%2,%3}, {%4,%5,%6,%7}, {%8,%9}, {%0,%1,%2,%3};\n"
        : "+f"(c[0]), "+f"(c[1]), "+f"(c[2]), "+f"(c[3])
        : "r"(a[0]), "r"(a[1]), "r"(a[2]), "r"(a[3]), "r"(b0), "r"(b1));
}

__device__ __forceinline__ void cp_async16(uint32_t saddr, const void* gptr) {
    asm volatile("cp.async.cg.shared.global [%0], [%1], 16;\n" :: "r"(saddr), "l"(gptr));
}
#define CP_COMMIT() asm volatile("cp.async.commit_group;\n")
#define CP_WAIT(N)  asm volatile("cp.async.wait_group %0;\n" :: "n"(N))

// stage-1 linear: h[r][col] = b1[col] + sum_i xs[r][i]*W1[i][col]; W1 cached in regs.
template<int DIN>
__device__ __forceinline__ void phaseA(const float* __restrict__ W1, const float* xs,
                                       const float* vb1, float* g, int tid) {
    const int col = tid & 255;
    const int rh  = tid >> 8;          // 0..1
    float w1c[DIN];
    #pragma unroll
    for (int i = 0; i < DIN; i++) w1c[i] = W1[i*256 + col];
    const float bias = vb1[col];
    #pragma unroll 4
    for (int r = rh; r < TILE_R; r += 2) {
        float acc = bias;
        #pragma unroll
        for (int i = 0; i < DIN; i++) acc = fmaf(xs[r*36 + i], w1c[i], acc);
        g[r*GSTRIDE + col] = acc;
    }
}

// Row LayerNorm over g[64][GSTRIDE] (256 cols). Optional exact GELU; optional
// tf32 pre-rounding of the stored value (for MMA A operand).
__device__ __forceinline__ void ln_rows(float* g, const float* gamma, const float* beta,
                                        bool do_gelu, bool round_a, int tid) {
    int warp = tid >> 5, lane = tid & 31;
    for (int r = warp; r < TILE_R; r += 16) {
        float v[8];
        float s = 0.f;
        #pragma unroll
        for (int j = 0; j < 8; j++) { v[j] = g[r*GSTRIDE + j*32 + lane]; s += v[j]; }
        #pragma unroll
        for (int o = 16; o; o >>= 1) s += __shfl_xor_sync(0xffffffffu, s, o);
        float mean = s * (1.f/256.f);
        float s2 = 0.f;
        #pragma unroll
        for (int j = 0; j < 8; j++) { float d = v[j] - mean; s2 += d*d; }
        #pragma unroll
        for (int o = 16; o; o >>= 1) s2 += __shfl_xor_sync(0xffffffffu, s2, o);
        float rstd = rsqrtf(s2 * (1.f/256.f) + 1e-5f);
        #pragma unroll
        for (int j = 0; j < 8; j++) {
            float hv = (v[j] - mean) * rstd * gamma[j*32 + lane] + beta[j*32 + lane];
            if (do_gelu) hv = 0.5f * hv * (1.f + erff(hv * 0.70710678f));
            if (round_a) hv = __uint_as_float(f2tf32(hv));
            g[r*GSTRIDE + j*32 + lane] = hv;
        }
    }
}

__device__ __forceinline__ void load_chunk(float* w2s, const float* W2, int k0, int tid) {
    uint32_t sbase = (uint32_t)__cvta_generic_to_shared(w2s);
    #pragma unroll
    for (int it = 0; it < 4; ++it) {
        int gidx = tid + it * NTHREADS;         // 0..2047
        int row  = gidx >> 6;                   // 0..31
        int c4   = (gidx & 63) << 2;            // 0,4,...,252
        cp_async16(sbase + (uint32_t)(row*WSTRIDE + c4) * 4,
                   W2 + (size_t)(k0 + row) * 256 + c4);
    }
    CP_COMMIT();
}

__global__ __launch_bounds__(NTHREADS, 1)
void phys_kernel(Params p) {
    const int part = blockIdx.y;
    const int r0 = blockIdx.x * TILE_R;
    const int tid = threadIdx.x;

    // ---- part 22: raw x passthrough ----
    if (part == 22) {
        for (int i = tid; i < TILE_R * XCOLS; i += NTHREADS) {
            int r = i / XCOLS, c = i - r * XCOLS;
            p.out[(size_t)(r0 + r) * OUTCOLS + 22*256 + c] =
                p.x[(size_t)(r0 + r) * XCOLS + c];
        }
        return;
    }

    extern __shared__ float smem[];
    float* g    = smem;                          // [64][260]
    float* buf0 = g    + TILE_R * GSTRIDE;       // [32][264]
    float* buf1 = buf0 + KCHUNK * WSTRIDE;       // [32][264]
    float* xs   = buf1 + KCHUNK * WSTRIDE;       // [64][36]
    float* vb1  = xs   + TILE_R * 36;
    float* vg1  = vb1 + 256;
    float* vbt1 = vg1 + 256;
    float* vb2  = vbt1 + 256;
    float* vg2  = vb2 + 256;
    float* vbt2 = vg2 + 256;

    const int ws   = c_wset[part];
    const int din  = c_din[part];
    const int ioff = c_in_off[part];
    const bool fln = (ws == 2 || ws == 3);
    const float* W2 = p.W2[ws];

    // Prefetch W2 chunks 0 and 1 immediately — covered by phase A + LN.
    load_chunk(buf0, W2, 0 * KCHUNK, tid);
    load_chunk(buf1, W2, 1 * KCHUNK, tid);

    // stage xs + per-feature vectors
    for (int i = tid; i < TILE_R * din; i += NTHREADS) {
        int r = i / din, c = i - r * din;
        xs[r*36 + c] = p.x[(size_t)(r0 + r) * XCOLS + ioff + c];
    }
    if (tid < 256) {
        vb1[tid]  = p.b1[ws][tid];
        vg1[tid]  = p.g1[ws][tid];
        vbt1[tid] = p.bt1[ws][tid];
        vb2[tid]  = p.b2[ws][tid];
        if (fln) { vg2[tid] = p.g2[ws][tid]; vbt2[tid] = p.bt2[ws][tid]; }
    }
    __syncthreads();

    // ---- Phase A: stage-1 linear (W1 in registers) ----
    switch (din) {
        case 3:  phaseA<3 >(p.W1[ws], xs, vb1, g, tid); break;
        case 4:  phaseA<4 >(p.W1[ws], xs, vb1, g, tid); break;
        case 9:  phaseA<9 >(p.W1[ws], xs, vb1, g, tid); break;
        default: phaseA<34>(p.W1[ws], xs, vb1, g, tid); break;
    }
    __syncthreads();

    // LN + exact GELU + tf32 pre-round (A operand)
    ln_rows(g, vg1, vbt1, /*gelu=*/true, /*round=*/true, tid);
    __syncthreads();

    // ---- Phase B: [64,256] @ W2[256,256], tf32 mma, 16 warps 2x8, warp tile 32x32 ----
    const int warp = tid >> 5, lane = tid & 31;
    const int rowGroup = warp >> 3;   // 0..1 -> rows rowGroup*32
    const int colGroup = warp & 7;    // 0..7 -> cols colGroup*32
    const int gid = lane >> 2, tig = lane & 3;

    float acc[2][4][4];
    #pragma unroll
    for (int mt = 0; mt < 2; mt++)
        #pragma unroll
        for (int nt = 0; nt < 4; nt++)
            #pragma unroll
            for (int q = 0; q < 4; q++) acc[mt][nt][q] = 0.f;

    #pragma unroll 1
    for (int c = 0; c < NCHUNKS; ++c) {
        if (c < NCHUNKS - 1) { CP_WAIT(1); } else { CP_WAIT(0); }
        __syncthreads();
        const float* w2s = (c & 1) ? buf1 : buf0;
        const int k0 = c * KCHUNK;

        #pragma unroll
        for (int ks = 0; ks < KCHUNK; ks += 8) {
            uint32_t a[2][4];
            #pragma unroll
            for (int mt = 0; mt < 2; mt++) {
                int rbase = rowGroup*32 + mt*16;
                const float* gr = g + (size_t)k0 + ks;
                a[mt][0] = __float_as_uint(gr[(rbase + gid    )*GSTRIDE + tig    ]);
                a[mt][1] = __float_as_uint(gr[(rbase + gid + 8)*GSTRIDE + tig    ]);
                a[mt][2] = __float_as_uint(gr[(rbase + gid    )*GSTRIDE + tig + 4]);
                a[mt][3] = __float_as_uint(gr[(rbase + gid + 8)*GSTRIDE + tig + 4]);
            }
            #pragma unroll
            for (int nt = 0; nt < 4; nt++) {
                int nbase = colGroup*32 + nt*8;
                uint32_t b0 = f2tf32(w2s[(ks + tig    )*WSTRIDE + nbase + gid]);
                uint32_t b1 = f2tf32(w2s[(ks + tig + 4)*WSTRIDE + nbase + gid]);
                mma_tf32(acc[0][nt], a[0], b0, b1);
                mma_tf32(acc[1][nt], a[1], b0, b1);
            }
        }
        __syncthreads();
        if (c + 2 < NCHUNKS)
            load_chunk((c & 1) ? buf1 : buf0, W2, (c + 2) * KCHUNK, tid);
    }

    // ---- Epilogue: +b2 into smem, optional final LN, coalesced store ----
    #pragma unroll
    for (int mt = 0; mt < 2; mt++) {
        int rbase = rowGroup*32 + mt*16;
        #pragma unroll
        for (int nt = 0; nt < 4; nt++) {
            int cc = colGroup*32 + nt*8 + tig*2;
            g[(rbase + gid    )*GSTRIDE + cc    ] = acc[mt][nt][0] + vb2[cc    ];
            g[(rbase + gid    )*GSTRIDE + cc + 1] = acc[mt][nt][1] + vb2[cc + 1];
            g[(rbase + gid + 8)*GSTRIDE + cc    ] = acc[mt][nt][2] + vb2[cc    ];
            g[(rbase + gid + 8)*GSTRIDE + cc + 1] = acc[mt][nt][3] + vb2[cc + 1];
        }
    }
    __syncthreads();

    if (fln) {
        ln_rows(g, vg2, vbt2, /*gelu=*/false, /*round=*/false, tid);
        __syncthreads();
    }

    const size_t col0 = (size_t)part * 256;
    const int col = tid & 255;
    const int rh  = tid >> 8;
    #pragma unroll 4
    for (int r = rh; r < TILE_R; r += 2)
        p.out[(size_t)(r0 + r) * OUTCOLS + col0 + col] = g[r*GSTRIDE + col];
}

extern "C" void kernel_launch(void* const* d_in, const int* in_sizes, int n_in,
                              void* d_out, int out_size) {
    const int w1i[4]  = {1, 7, 21, 13};
    const int b1i[4]  = {2, 8, 22, 14};
    const int g1i[4]  = {3, 9, 23, 15};
    const int bt1i[4] = {4, 10, 24, 16};
    const int w2i[4]  = {5, 11, 25, 17};
    const int b2i[4]  = {6, 12, 26, 18};

    Params p;
    p.x = (const float*)d_in[0];
    for (int s = 0; s < 4; s++) {
        p.W1[s]  = (const float*)d_in[w1i[s]];
        p.b1[s]  = (const float*)d_in[b1i[s]];
        p.g1[s]  = (const float*)d_in[g1i[s]];
        p.bt1[s] = (const float*)d_in[bt1i[s]];
        p.W2[s]  = (const float*)d_in[w2i[s]];
        p.b2[s]  = (const float*)d_in[b2i[s]];
        p.g2[s]  = nullptr;
        p.bt2[s] = nullptr;
    }
    p.g2[2]  = (const float*)d_in[27];
    p.bt2[2] = (const float*)d_in[28];
    p.g2[3]  = (const float*)d_in[19];
    p.bt2[3] = (const float*)d_in[20];
    p.out = (float*)d_out;

    int rows = in_sizes[0] / XCOLS;
    p.rows = rows;
    int rtiles = (rows + TILE_R - 1) / TILE_R;

    size_t smem_bytes = (size_t)(TILE_R * GSTRIDE + 2 * KCHUNK * WSTRIDE +
                                 TILE_R * 36 + 6 * 256) * sizeof(float);
    cudaFuncSetAttribute(phys_kernel, cudaFuncAttributeMaxDynamicSharedMemorySize,
                         (int)smem_bytes);

    dim3 grid(rtiles, 23);
    phys_kernel<<<grid, NTHREADS, smem_bytes>>>(p);
}

// round 6
// speedup vs baseline: 2.3929x; 1.1489x over previous
#include <cuda_runtime.h>
#include <cstdint>
#include <math.h>

#define XCOLS    111
#define OUTCOLS  (22*256 + 111)   // 5743
#define TILE_R   32
#define AS       264              // A-tile row stride (floats); 264 mod 32 == 8
#define KCHUNK   32               // K per chunk = 4 ksteps of 8
#define NCHUNKS  8
#define NTHREADS 256

__constant__ int c_in_off[22] = {0,3,6,9,43,46,49,52,61,64,67,70,74,77,80,83,92,95,98,101,105,108};
__constant__ int c_din[22]    = {3,3,3,34,3,3,3, 9,3,3,3, 4,3,3,3, 9,3,3,3,  4,  3,  3};
__constant__ int c_wset[22]   = {0,0,0, 3,0,0,0, 1,0,0,0, 2,0,0,0, 1,0,0,0,  2,  0,  0};

// W2 pre-rounded to tf32 AND pre-permuted into fragment order:
// w2p[ws][ks(0..31)][n(0..255)][q(0..7)] where q = t*2+h holds W2[ks*8+t+h*4][n].
// A (ks,n,tig) B-fragment (b0,b1) is then one contiguous 8-byte pair at q=2*tig.
__device__ float g_w2p[4 * 256 * 256];

struct Params {
    const float* x;
    const float* W1[4];
    const float* b1[4];
    const float* g1[4];
    const float* bt1[4];
    const float* b2[4];
    const float* g2[4];
    const float* bt2[4];
    float* out;
};

__device__ __forceinline__ uint32_t f2tf32(float v) {
    uint32_t r; asm("cvt.rna.tf32.f32 %0, %1;" : "=r"(r) : "f"(v)); return r;
}

__device__ __forceinline__ void mma_tf32(float c[4], uint32_t a0, uint32_t a1,
                                         uint32_t a2, uint32_t a3,
                                         uint32_t b0, uint32_t b1) {
    asm volatile(
        "mma.sync.aligned.m16n8k8.row.col.f32.tf32.tf32.f32 "
        "{%0,%1,%2,%3}, {%4,%5,%6,%7}, {%8,%9}, {%0,%1,%2,%3};\n"
        : "+f"(c[0]), "+f"(c[1]), "+f"(c[2]), "+f"(c[3])
        : "r"(a0), "r"(a1), "r"(a2), "r"(a3), "r"(b0), "r"(b1));
}

__device__ __forceinline__ void cp_async16(uint32_t saddr, const void* gptr) {
    asm volatile("cp.async.cg.shared.global [%0], [%1], 16;\n" :: "r"(saddr), "l"(gptr));
}
#define CP_COMMIT() asm volatile("cp.async.commit_group;\n")
#define CP_WAIT(N)  asm volatile("cp.async.wait_group %0;\n" :: "n"(N))

// column permutation within an 8-group: c -> (c&3)*2 + ((c>>2)&1)
__device__ __forceinline__ int permcol(int c) {
    return (c & ~7) | (((c & 3) << 1) | ((c >> 2) & 1));
}

// ---------------- phase A: stage-1 linear into permuted A tile ----------------
template<int DIN>
__device__ __forceinline__ void phaseA(const float* __restrict__ W1,
                                       const float* __restrict__ b1,
                                       const float* xs, float* ga, int tid) {
    const int col = tid;                 // 256 threads, one col each
    float w1c[DIN];
    #pragma unroll
    for (int i = 0; i < DIN; i++) w1c[i] = __ldg(W1 + i*256 + col);
    const float bias = __ldg(b1 + col);
    const int pc = permcol(col);
    #pragma unroll 4
    for (int r = 0; r < TILE_R; ++r) {
        float acc = bias;
        #pragma unroll
        for (int i = 0; i < DIN; i++) acc = fmaf(xs[r*36 + i], w1c[i], acc);
        ga[r*AS + pc] = acc;
    }
}

// LN + exact GELU + tf32 round, in-place on permuted A tile. 8 warps, rows w, w+8, ...
__device__ __forceinline__ void ln_gelu_perm(float* ga, const float* __restrict__ gamma,
                                             const float* __restrict__ beta, int tid) {
    int warp = tid >> 5, lane = tid & 31;
    for (int r = warp; r < TILE_R; r += 8) {
        int idx[8];
        float v[8];
        float s = 0.f;
        #pragma unroll
        for (int j = 0; j < 8; j++) {
            idx[j] = r*AS + permcol(j*32 + lane);
            v[j] = ga[idx[j]];
            s += v[j];
        }
        #pragma unroll
        for (int o = 16; o; o >>= 1) s += __shfl_xor_sync(0xffffffffu, s, o);
        float mean = s * (1.f/256.f);
        float s2 = 0.f;
        #pragma unroll
        for (int j = 0; j < 8; j++) { float d = v[j] - mean; s2 += d*d; }
        #pragma unroll
        for (int o = 16; o; o >>= 1) s2 += __shfl_xor_sync(0xffffffffu, s2, o);
        float rstd = rsqrtf(s2 * (1.f/256.f) + 1e-5f);
        #pragma unroll
        for (int j = 0; j < 8; j++) {
            int c = j*32 + lane;
            float hv = (v[j] - mean) * rstd * __ldg(gamma + c) + __ldg(beta + c);
            hv = 0.5f * hv * (1.f + erff(hv * 0.70710678f));
            ga[idx[j]] = __uint_as_float(f2tf32(hv));
        }
    }
}

// plain-layout LN for the final LayerNorm (epilogue staging, stride AS)
__device__ __forceinline__ void ln_plain(float* g, const float* __restrict__ gamma,
                                         const float* __restrict__ beta, int tid) {
    int warp = tid >> 5, lane = tid & 31;
    for (int r = warp; r < TILE_R; r += 8) {
        float v[8];
        float s = 0.f;
        #pragma unroll
        for (int j = 0; j < 8; j++) { v[j] = g[r*AS + j*32 + lane]; s += v[j]; }
        #pragma unroll
        for (int o = 16; o; o >>= 1) s += __shfl_xor_sync(0xffffffffu, s, o);
        float mean = s * (1.f/256.f);
        float s2 = 0.f;
        #pragma unroll
        for (int j = 0; j < 8; j++) { float d = v[j] - mean; s2 += d*d; }
        #pragma unroll
        for (int o = 16; o; o >>= 1) s2 += __shfl_xor_sync(0xffffffffu, s2, o);
        float rstd = rsqrtf(s2 * (1.f/256.f) + 1e-5f);
        #pragma unroll
        for (int j = 0; j < 8; j++)
            g[r*AS + j*32 + lane] = (v[j] - mean) * rstd * __ldg(gamma + j*32 + lane)
                                  + __ldg(beta + j*32 + lane);
    }
}

// B chunk: 8192 contiguous floats (4 ksteps x 256 n x 8) -> linear smem. Coalesced.
__device__ __forceinline__ void load_chunk(uint32_t sbase, const float* src, int tid) {
    #pragma unroll
    for (int it = 0; it < 8; ++it) {
        int i = (tid + it * NTHREADS) << 2;   // float index, 16B-aligned steps
        cp_async16(sbase + (uint32_t)i * 4u, src + i);
    }
}

// ---------------- kernels ----------------
__global__ void prep_w2(const float* __restrict__ a, const float* __restrict__ b,
                        const float* __restrict__ c, const float* __restrict__ d) {
    int i = blockIdx.x * blockDim.x + threadIdx.x;     // 0..262143
    if (i >= 4*65536) return;
    const float* W = (i >> 16) == 0 ? a : (i >> 16) == 1 ? b : (i >> 16) == 2 ? c : d;
    int rem = i & 65535;
    int ks  = rem >> 11;        // 0..31
    int slot = rem & 2047;
    int n  = slot >> 3;         // 0..255
    int q  = slot & 7;
    int t  = q >> 1, h = q & 1;
    int k  = ks*8 + t + h*4;
    g_w2p[i] = __uint_as_float(f2tf32(W[k*256 + n]));
}

__global__ __launch_bounds__(NTHREADS, 2)
void phys_kernel(Params p) {
    const int part = blockIdx.y;
    const int r0 = blockIdx.x * TILE_R;
    const int tid = threadIdx.x;

    // ---- part 22: raw x passthrough ----
    if (part == 22) {
        for (int i = tid; i < TILE_R * XCOLS; i += NTHREADS) {
            int r = i / XCOLS, c = i - r * XCOLS;
            p.out[(size_t)(r0 + r) * OUTCOLS + 22*256 + c] =
                p.x[(size_t)(r0 + r) * XCOLS + c];
        }
        return;
    }

    extern __shared__ __align__(16) float smem[];
    float* b0s = smem;                 // 8192 floats (32 KB)
    float* b1s = b0s + 8192;           // 8192 floats
    float* ga  = b1s + 8192;           // 32*264 floats
    float* xs  = ga + TILE_R * AS;     // 32*36 floats
    const uint32_t sb0 = (uint32_t)__cvta_generic_to_shared(b0s);
    const uint32_t sb1 = (uint32_t)__cvta_generic_to_shared(b1s);

    const int warp = tid >> 5, lane = tid & 31;
    const int gid = lane >> 2, tig = lane & 3;
    const int ws   = c_wset[part];
    const int din  = c_din[part];
    const int ioff = c_in_off[part];
    const bool fln = (ws == 2 || ws == 3);
    const float* W2p = &g_w2p[ws * 65536];

    // prefetch B chunks 0,1 (each 8192 floats, contiguous)
    load_chunk(sb0, W2p, tid);          CP_COMMIT();
    load_chunk(sb1, W2p + 8192, tid);   CP_COMMIT();

    // stage xs
    for (int i = tid; i < TILE_R * din; i += NTHREADS) {
        int r = i / din, c = i - r * din;
        xs[r*36 + c] = p.x[(size_t)(r0 + r) * XCOLS + ioff + c];
    }
    __syncthreads();

    // phase A (stage-1 linear) into permuted A tile, then LN+GELU+tf32 round
    switch (din) {
        case 3:  phaseA<3 >(p.W1[ws], p.b1[ws], xs, ga, tid); break;
        case 4:  phaseA<4 >(p.W1[ws], p.b1[ws], xs, ga, tid); break;
        case 9:  phaseA<9 >(p.W1[ws], p.b1[ws], xs, ga, tid); break;
        default: phaseA<34>(p.W1[ws], p.b1[ws], xs, ga, tid); break;
    }
    __syncthreads();
    ln_gelu_perm(ga, p.g1[ws], p.bt1[ws], tid);
    __syncthreads();

    // ---- mainloop: [32,256] @ W2[256,256], warp tile 32x32 (1x8 warps) ----
    float acc[2][4][4];
    #pragma unroll
    for (int mt = 0; mt < 2; mt++)
        #pragma unroll
        for (int nt = 0; nt < 4; nt++)
            #pragma unroll
            for (int q = 0; q < 4; q++) acc[mt][nt][q] = 0.f;

    // per-thread base pointers (A rows gid, gid+8, gid+16, gid+24; pair at 2*tig)
    const float* pa0 = ga + (gid     )*AS + 2*tig;
    const float* pa1 = ga + (gid +  8)*AS + 2*tig;
    const float* pa2 = ga + (gid + 16)*AS + 2*tig;
    const float* pa3 = ga + (gid + 24)*AS + 2*tig;
    const int boff = (warp*32 + gid)*8 + 2*tig;       // B pair offset within [n][8]

    #pragma unroll 1
    for (int c = 0; c < NCHUNKS; ++c) {
        if (c < NCHUNKS - 1) { CP_WAIT(1); } else { CP_WAIT(0); }
        __syncthreads();
        const float* wb = (c & 1) ? b1s : b0s;

        #pragma unroll
        for (int ksl = 0; ksl < 4; ++ksl) {
            const int k8 = (c*4 + ksl) * 8;
            float2 A0 = *(const float2*)(pa0 + k8);
            float2 A1 = *(const float2*)(pa1 + k8);
            float2 A2 = *(const float2*)(pa2 + k8);
            float2 A3 = *(const float2*)(pa3 + k8);
            const float* wk = wb + ksl*2048 + boff;
            #pragma unroll
            for (int nt = 0; nt < 4; nt++) {
                float2 B = *(const float2*)(wk + nt*64);   // 8 cols * 8 floats
                mma_tf32(acc[0][nt],
                         __float_as_uint(A0.x), __float_as_uint(A1.x),
                         __float_as_uint(A0.y), __float_as_uint(A1.y),
                         __float_as_uint(B.x),  __float_as_uint(B.y));
                mma_tf32(acc[1][nt],
                         __float_as_uint(A2.x), __float_as_uint(A3.x),
                         __float_as_uint(A2.y), __float_as_uint(A3.y),
                         __float_as_uint(B.x),  __float_as_uint(B.y));
            }
        }
        __syncthreads();
        if (c + 2 < NCHUNKS) {
            load_chunk((c & 1) ? sb1 : sb0, W2p + (size_t)(c + 2) * 8192, tid);
            CP_COMMIT();
        }
    }

    // ---- epilogue: +b2 into plain-layout staging (reuse ga), LN if needed, store ----
    const float* b2 = p.b2[ws];
    #pragma unroll
    for (int mt = 0; mt < 2; mt++) {
        int rb = mt*16;
        #pragma unroll
        for (int nt = 0; nt < 4; nt++) {
            int cc = warp*32 + nt*8 + tig*2;
            ga[(rb + gid    )*AS + cc    ] = acc[mt][nt][0] + __ldg(b2 + cc    );
            ga[(rb + gid    )*AS + cc + 1] = acc[mt][nt][1] + __ldg(b2 + cc + 1);
            ga[(rb + gid + 8)*AS + cc    ] = acc[mt][nt][2] + __ldg(b2 + cc    );
            ga[(rb + gid + 8)*AS + cc + 1] = acc[mt][nt][3] + __ldg(b2 + cc + 1);
        }
    }
    __syncthreads();

    if (fln) {
        ln_plain(ga, p.g2[ws], p.bt2[ws], tid);
        __syncthreads();
    }

    const size_t col0 = (size_t)part * 256;
    #pragma unroll 4
    for (int r = 0; r < TILE_R; ++r)
        p.out[(size_t)(r0 + r) * OUTCOLS + col0 + tid] = ga[r*AS + tid];
}

extern "C" void kernel_launch(void* const* d_in, const int* in_sizes, int n_in,
                              void* d_out, int out_size) {
    const int w1i[4]  = {1, 7, 21, 13};
    const int b1i[4]  = {2, 8, 22, 14};
    const int g1i[4]  = {3, 9, 23, 15};
    const int bt1i[4] = {4, 10, 24, 16};
    const int w2i[4]  = {5, 11, 25, 17};
    const int b2i[4]  = {6, 12, 26, 18};

    Params p;
    p.x = (const float*)d_in[0];
    for (int s = 0; s < 4; s++) {
        p.W1[s]  = (const float*)d_in[w1i[s]];
        p.b1[s]  = (const float*)d_in[b1i[s]];
        p.g1[s]  = (const float*)d_in[g1i[s]];
        p.bt1[s] = (const float*)d_in[bt1i[s]];
        p.b2[s]  = (const float*)d_in[b2i[s]];
        p.g2[s]  = nullptr;
        p.bt2[s] = nullptr;
    }
    p.g2[2]  = (const float*)d_in[27];
    p.bt2[2] = (const float*)d_in[28];
    p.g2[3]  = (const float*)d_in[19];
    p.bt2[3] = (const float*)d_in[20];
    p.out = (float*)d_out;

    // pre-round (tf32 RNA) + pre-permute W2 into fragment order
    prep_w2<<<1024, 256>>>((const float*)d_in[w2i[0]], (const float*)d_in[w2i[1]],
                           (const float*)d_in[w2i[2]], (const float*)d_in[w2i[3]]);

    int rows = in_sizes[0] / XCOLS;
    int rtiles = (rows + TILE_R - 1) / TILE_R;

    size_t smem_bytes = (size_t)(2*8192 + TILE_R*AS + TILE_R*36) * sizeof(float);
    cudaFuncSetAttribute(phys_kernel, cudaFuncAttributeMaxDynamicSharedMemorySize,
                         (int)smem_bytes);

    dim3 grid(rtiles, 23);
    phys_kernel<<<grid, NTHREADS, smem_bytes>>>(p);
}